// round 13
// baseline (speedup 1.0000x reference)
#include <cuda_runtime.h>
#include <cuda_bf16.h>
#include <cstdint>

#define D_MODEL 1024
#define SEQ     2048
#define BATCH   4
#define NHEAD   16
#define DHEAD   64
#define MTOT    (BATCH*SEQ)   // 8192
#define LN_EPS  1e-5f

// ---------------------------------------------------------------------------
// Scratch (no cudaMalloc allowed). bf16 operands, fp32 where accuracy matters.
// ---------------------------------------------------------------------------
__device__ __nv_bfloat16 g_qh[(size_t)MTOT * D_MODEL];
__device__ __nv_bfloat16 g_kh[(size_t)MTOT * D_MODEL];
__device__ __nv_bfloat16 g_vh[(size_t)MTOT * D_MODEL];
__device__ __nv_bfloat16 g_ah[(size_t)MTOT * D_MODEL];   // attention output
__device__ __nv_bfloat16 g_bxh[(size_t)MTOT * D_MODEL];  // bf16 batch
__device__ __nv_bfloat16 g_wqkv[(size_t)3 * D_MODEL * D_MODEL]; // packed q,k,v
__device__ __nv_bfloat16 g_woh[(size_t)D_MODEL * D_MODEL];
__device__ float g_x[(size_t)MTOT * D_MODEL];            // residual sum (fp32)

// ---------------------------------------------------------------------------
// Helpers
// ---------------------------------------------------------------------------
__device__ __forceinline__ uint32_t s2u(const void* p) {
    uint32_t a;
    asm("{ .reg .u64 t; cvta.to.shared.u64 t, %1; cvt.u32.u64 %0, t; }"
        : "=r"(a) : "l"(p));
    return a;
}

#define LDSM4(f0,f1,f2,f3,addr) \
    asm volatile("ldmatrix.sync.aligned.m8n8.x4.shared.b16 {%0,%1,%2,%3}, [%4];" \
                 : "=r"(f0), "=r"(f1), "=r"(f2), "=r"(f3) : "r"(addr))

#define LDSM4T(f0,f1,f2,f3,addr) \
    asm volatile("ldmatrix.sync.aligned.m8n8.x4.trans.shared.b16 {%0,%1,%2,%3}, [%4];" \
                 : "=r"(f0), "=r"(f1), "=r"(f2), "=r"(f3) : "r"(addr))

#define MMA_BF16(d, a, b0, b1) \
    asm volatile("mma.sync.aligned.m16n8k16.row.col.f32.bf16.bf16.f32 " \
                 "{%0,%1,%2,%3}, {%4,%5,%6,%7}, {%8,%9}, {%0,%1,%2,%3};" \
                 : "+f"((d)[0]), "+f"((d)[1]), "+f"((d)[2]), "+f"((d)[3]) \
                 : "r"((a)[0]), "r"((a)[1]), "r"((a)[2]), "r"((a)[3]), \
                   "r"(b0), "r"(b1))

#define CP16(dst, src) \
    asm volatile("cp.async.cg.shared.global [%0], [%1], 16;" \
                 :: "r"(dst), "l"(src) : "memory")

__device__ __forceinline__ uint32_t packbf(float a, float b) {
    __nv_bfloat162 h = __floats2bfloat162_rn(a, b);
    return *(uint32_t*)&h;
}

// Raw MUFU exp2 (single EX2, no pre-multiply)
__device__ __forceinline__ float ex2(float x) {
    float r;
    asm("ex2.approx.f32 %0, %1;" : "=f"(r) : "f"(x));
    return r;
}

// ---------------------------------------------------------------------------
// Single fused fp32 -> bf16 conversion kernel
// ---------------------------------------------------------------------------
__global__ __launch_bounds__(256)
void conv_all_kernel(const float* __restrict__ batch,
                     const float* __restrict__ wq, const float* __restrict__ wk,
                     const float* __restrict__ wv, const float* __restrict__ wo,
                     __nv_bfloat16* __restrict__ bxh,
                     __nv_bfloat16* __restrict__ wqkv,
                     __nv_bfloat16* __restrict__ woh)
{
    const int nb4 = MTOT * D_MODEL / 4;
    const int nw4 = D_MODEL * D_MODEL / 4;
    int i = blockIdx.x * blockDim.x + threadIdx.x;

    const float* src;
    __nv_bfloat16* dst;
    int j;
    if (i < nb4) {
        src = batch; dst = bxh; j = i;
    } else {
        int k = i - nb4;
        if (k < 3 * nw4) {
            int w = k / nw4;
            j = k - w * nw4;
            src = (w == 0) ? wq : (w == 1) ? wk : wv;
            dst = wqkv + (size_t)w * D_MODEL * D_MODEL;
        } else {
            j = k - 3 * nw4;
            if (j >= nw4) return;
            src = wo; dst = woh;
        }
    }
    float4 f = ((const float4*)src)[j];
    ((__nv_bfloat162*)dst)[j * 2]     = __floats2bfloat162_rn(f.x, f.y);
    ((__nv_bfloat162*)dst)[j * 2 + 1] = __floats2bfloat162_rn(f.z, f.w);
}

// ---------------------------------------------------------------------------
// QKV GEMM (unchanged — measured plateau): CTA 128x128, 128 threads = 4 warps,
// warp tile 64x64, BK=64, NS=3 cp.async ring, bf16 outputs routed by segment.
// ---------------------------------------------------------------------------
#define GPH   72                    // halves per smem row (64 data + 8 pad)
#define GSTGB (128 * GPH * 2)       // 18432 bytes per operand per stage
#define GSM   (3 * 2 * GSTGB)       // 110592 bytes dynamic smem

__global__ __launch_bounds__(128, 2)
void gemm_qkv(const __nv_bfloat16* __restrict__ A, const __nv_bfloat16* __restrict__ W,
              const float* __restrict__ b0p, const float* __restrict__ b1p,
              const float* __restrict__ b2p,
              __nv_bfloat16* __restrict__ o0p, __nv_bfloat16* __restrict__ o1p,
              __nv_bfloat16* __restrict__ o2p,
              int M, int K)
{
    extern __shared__ __align__(16) char gsm[];
    const uint32_t sA = s2u(gsm);
    const uint32_t sB = sA + 3 * GSTGB;

    const int tid  = threadIdx.x;
    const int wid  = tid >> 5;
    const int lane = tid & 31;
    const int wm   = wid & 1;
    const int wn   = wid >> 1;
    const int m0   = blockIdx.y * 128;
    const int n0   = blockIdx.x * 128;
    const int NCH  = K / 64;               // 16

    int seg = n0 >> 10;
    const float* bias = (seg == 0) ? b0p : (seg == 1) ? b1p : b2p;
    __nv_bfloat16* Cb = (seg == 0) ? o0p : (seg == 1) ? o1p : o2p;
    int nloc0 = n0 & 1023;

    const int r_ld = tid >> 3;
    const int g_ld = tid & 7;
    const __nv_bfloat16* Abase = A + (size_t)m0 * K + g_ld * 8;
    const __nv_bfloat16* Wbase = W + (size_t)n0 * K + g_ld * 8;

    auto issue = [&](int c) {
        if (c < NCH) {
            int st = c - (c / 3) * 3;
            uint32_t da = sA + st * GSTGB;
            uint32_t db = sB + st * GSTGB;
            long ko = (long)c * 64;
#pragma unroll
            for (int q = 0; q < 8; q++) {
                int row = r_ld + q * 16;
                CP16(da + row * (GPH * 2) + g_ld * 16, Abase + (size_t)row * K + ko);
                CP16(db + row * (GPH * 2) + g_ld * 16, Wbase + (size_t)row * K + ko);
            }
        }
        asm volatile("cp.async.commit_group;" ::: "memory");
    };

    float acc[4][8][4];
#pragma unroll
    for (int i = 0; i < 4; i++)
#pragma unroll
        for (int j = 0; j < 8; j++)
#pragma unroll
            for (int k = 0; k < 4; k++) acc[i][j][k] = 0.0f;

    const int laneA_r = ((lane >> 3) & 1) * 8 + (lane & 7);
    const int laneA_g = lane >> 4;
    const int laneB_r = (lane >> 4) * 8 + (lane & 7);
    const int laneB_g = (lane >> 3) & 1;

    issue(0); issue(1);

    for (int c = 0; c < NCH; c++) {
        asm volatile("cp.async.wait_group 1;" ::: "memory");
        __syncthreads();
        issue(c + 2);

        int st = c - (c / 3) * 3;
        uint32_t aSt = sA + st * GSTGB;
        uint32_t bSt = sB + st * GSTGB;

#pragma unroll
        for (int j = 0; j < 4; j++) {
            uint32_t aF[4][4], bF[4][4];
#pragma unroll
            for (int mt = 0; mt < 4; mt++) {
                uint32_t addr = aSt + (wm * 64 + mt * 16 + laneA_r) * (GPH * 2)
                                    + (laneA_g + 2 * j) * 16;
                LDSM4(aF[mt][0], aF[mt][1], aF[mt][2], aF[mt][3], addr);
            }
#pragma unroll
            for (int np = 0; np < 4; np++) {
                uint32_t addr = bSt + (wn * 64 + np * 16 + laneB_r) * (GPH * 2)
                                    + (laneB_g + 2 * j) * 16;
                LDSM4(bF[np][0], bF[np][1], bF[np][2], bF[np][3], addr);
            }
#pragma unroll
            for (int mt = 0; mt < 4; mt++) {
#pragma unroll
                for (int nt = 0; nt < 8; nt++) {
                    MMA_BF16(acc[mt][nt], aF[mt],
                             bF[nt >> 1][(nt & 1) * 2], bF[nt >> 1][(nt & 1) * 2 + 1]);
                }
            }
        }
    }

    const int rb = lane >> 2;
    const int cb = (lane & 3) * 2;
#pragma unroll
    for (int mt = 0; mt < 4; mt++) {
#pragma unroll
        for (int nt = 0; nt < 8; nt++) {
            int nl = nloc0 + wn * 64 + nt * 8 + cb;
            float2 bv = *(const float2*)(bias + nl);
            int row0 = m0 + wm * 64 + mt * 16 + rb;
            int row1 = row0 + 8;
            *(__nv_bfloat162*)(Cb + (size_t)row0 * D_MODEL + nl) =
                __floats2bfloat162_rn(acc[mt][nt][0] + bv.x, acc[mt][nt][1] + bv.y);
            *(__nv_bfloat162*)(Cb + (size_t)row1 * D_MODEL + nl) =
                __floats2bfloat162_rn(acc[mt][nt][2] + bv.x, acc[mt][nt][3] + bv.y);
        }
    }
}

// ---------------------------------------------------------------------------
// Out-projection GEMM (+bias +fp32 residual -> fp32): 256 threads = 8 warps,
// warp grid 2(m) x 4(n), warp tile 64x32 (acc = 64 regs -> no spill).
// Same BK=64, NS=3 cp.async ring, smem layout as gemm_qkv.
// ---------------------------------------------------------------------------
__global__ __launch_bounds__(256, 2)
void gemm_out(const __nv_bfloat16* __restrict__ A, const __nv_bfloat16* __restrict__ W,
              const float* __restrict__ bias,
              const float* __restrict__ resid, float* __restrict__ Cf,
              int M, int K)
{
    extern __shared__ __align__(16) char gsm[];
    const uint32_t sA = s2u(gsm);
    const uint32_t sB = sA + 3 * GSTGB;

    const int tid  = threadIdx.x;
    const int wid  = tid >> 5;
    const int lane = tid & 31;
    const int wm   = wid & 1;        // 0..1
    const int wn   = wid >> 1;       // 0..3
    const int m0   = blockIdx.y * 128;
    const int n0   = blockIdx.x * 128;
    const int NCH  = K / 64;               // 16

    const int g_ld = tid & 7;        // granule
    const int r4   = tid >> 3;       // 0..31 base row
    const __nv_bfloat16* Abase = A + (size_t)m0 * K + g_ld * 8;
    const __nv_bfloat16* Wbase = W + (size_t)n0 * K + g_ld * 8;

    auto issue = [&](int c) {
        if (c < NCH) {
            int st = c - (c / 3) * 3;
            uint32_t da = sA + st * GSTGB;
            uint32_t db = sB + st * GSTGB;
            long ko = (long)c * 64;
#pragma unroll
            for (int q = 0; q < 4; q++) {
                int row = r4 + q * 32;
                CP16(da + row * (GPH * 2) + g_ld * 16, Abase + (size_t)row * K + ko);
                CP16(db + row * (GPH * 2) + g_ld * 16, Wbase + (size_t)row * K + ko);
            }
        }
        asm volatile("cp.async.commit_group;" ::: "memory");
    };

    float acc[4][4][4];
#pragma unroll
    for (int i = 0; i < 4; i++)
#pragma unroll
        for (int j = 0; j < 4; j++)
#pragma unroll
            for (int k = 0; k < 4; k++) acc[i][j][k] = 0.0f;

    const int laneA_r = ((lane >> 3) & 1) * 8 + (lane & 7);
    const int laneA_g = lane >> 4;
    const int laneB_r = (lane >> 4) * 8 + (lane & 7);
    const int laneB_g = (lane >> 3) & 1;

    issue(0); issue(1);

    for (int c = 0; c < NCH; c++) {
        asm volatile("cp.async.wait_group 1;" ::: "memory");
        __syncthreads();
        issue(c + 2);

        int st = c - (c / 3) * 3;
        uint32_t aSt = sA + st * GSTGB;
        uint32_t bSt = sB + st * GSTGB;

#pragma unroll
        for (int j = 0; j < 4; j++) {
            uint32_t aF[4][4], bF[2][4];
#pragma unroll
            for (int mt = 0; mt < 4; mt++) {
                uint32_t addr = aSt + (wm * 64 + mt * 16 + laneA_r) * (GPH * 2)
                                    + (laneA_g + 2 * j) * 16;
                LDSM4(aF[mt][0], aF[mt][1], aF[mt][2], aF[mt][3], addr);
            }
#pragma unroll
            for (int np = 0; np < 2; np++) {
                uint32_t addr = bSt + (wn * 32 + np * 16 + laneB_r) * (GPH * 2)
                                    + (laneB_g + 2 * j) * 16;
                LDSM4(bF[np][0], bF[np][1], bF[np][2], bF[np][3], addr);
            }
#pragma unroll
            for (int mt = 0; mt < 4; mt++) {
#pragma unroll
                for (int nt = 0; nt < 4; nt++) {
                    MMA_BF16(acc[mt][nt], aF[mt],
                             bF[nt >> 1][(nt & 1) * 2], bF[nt >> 1][(nt & 1) * 2 + 1]);
                }
            }
        }
    }

    const int rb = lane >> 2;
    const int cb = (lane & 3) * 2;
#pragma unroll
    for (int mt = 0; mt < 4; mt++) {
#pragma unroll
        for (int nt = 0; nt < 4; nt++) {
            int nl = n0 + wn * 32 + nt * 8 + cb;
            float2 bv = *(const float2*)(bias + nl);
            int row0 = m0 + wm * 64 + mt * 16 + rb;
            int row1 = row0 + 8;
            float2 r0 = *(const float2*)(resid + (size_t)row0 * D_MODEL + nl);
            float2 r1 = *(const float2*)(resid + (size_t)row1 * D_MODEL + nl);
            *(float2*)(Cf + (size_t)row0 * D_MODEL + nl) =
                make_float2(acc[mt][nt][0] + bv.x + r0.x, acc[mt][nt][1] + bv.y + r0.y);
            *(float2*)(Cf + (size_t)row1 * D_MODEL + nl) =
                make_float2(acc[mt][nt][2] + bv.x + r1.x, acc[mt][nt][3] + bv.y + r1.y);
        }
    }
}

// ---------------------------------------------------------------------------
// bf16 tensor-core flash attention (fp32 accum + softmax), exp2 domain.
// UNCHANGED from Round 10/11 (at the mma.sync plateau).
// ---------------------------------------------------------------------------
#define APH    72
#define APB    (APH * 2)            // 144 bytes row pitch
#define KSTG   (64 * APB)           // 9216 per stage
#define AOFF_K  0
#define AOFF_V  (3 * KSTG)           // 27648
#define AOFF_Q  (6 * KSTG)           // 55296
#define ASM_TOTAL (AOFF_Q + 128 * APB) // 73728

#define SCALE_LOG2 0.1803368801111244f   // 0.125 * log2(e)

__global__ __launch_bounds__(256, 2)
void attn_bf16(const __nv_bfloat16* __restrict__ Q,
               const __nv_bfloat16* __restrict__ Kg,
               const __nv_bfloat16* __restrict__ Vg,
               __nv_bfloat16* __restrict__ Og)
{
    extern __shared__ __align__(16) char asmem[];
    const uint32_t sb = s2u(asmem);
    const uint32_t sK = sb + AOFF_K;
    const uint32_t sV = sb + AOFF_V;
    const uint32_t sQ = sb + AOFF_Q;
    __nv_bfloat16* smQ = (__nv_bfloat16*)(asmem + AOFF_Q);

    const int qt   = blockIdx.x;
    const int h    = blockIdx.y;
    const int b    = blockIdx.z;
    const int tid  = threadIdx.x;
    const int warp = tid >> 5;
    const int lane = tid & 31;

    const size_t base = ((size_t)b * SEQ) * D_MODEL + (size_t)h * DHEAD;
    const int NT = SEQ / 64;  // 32

    auto issue_kv = [&](int kt) {
        if (kt < NT) {
            int st = kt - (kt / 3) * 3;
            uint32_t kd = sK + st * KSTG;
            uint32_t vd = sV + st * KSTG;
            const __nv_bfloat16* kp = Kg + base + (size_t)(kt * 64) * D_MODEL;
            const __nv_bfloat16* vp = Vg + base + (size_t)(kt * 64) * D_MODEL;
#pragma unroll
            for (int q = 0; q < 2; q++) {
                int id = tid + q * 256;
                int r = id >> 3, g = id & 7;
                CP16(kd + r * APB + g * 16, kp + (size_t)r * D_MODEL + g * 8);
                CP16(vd + r * APB + g * 16, vp + (size_t)r * D_MODEL + g * 8);
            }
        }
        asm volatile("cp.async.commit_group;" ::: "memory");
    };

    issue_kv(0);
    issue_kv(1);

    for (int i = tid; i < 1024; i += 256) {
        int r = i >> 3;
        int g = i & 7;
        uint4 f = *(const uint4*)(Q + base + (size_t)(qt * 128 + r) * D_MODEL + g * 8);
        *(uint4*)(smQ + r * APH + g * 8) = f;
    }
    __syncthreads();

    const int laneA_r = ((lane >> 3) & 1) * 8 + (lane & 7);
    const int laneA_g = lane >> 4;
    const int laneB_r = (lane >> 4) * 8 + (lane & 7);
    const int laneB_g = (lane >> 3) & 1;
    const int laneV_key  = ((lane >> 3) & 1) * 8 + (lane & 7);
    const int laneV_doff = (lane >> 4) * 8;

    uint32_t qF[4][4];
#pragma unroll
    for (int j = 0; j < 4; j++) {
        LDSM4(qF[j][0], qF[j][1], qF[j][2], qF[j][3],
              sQ + (warp * 16 + laneA_r) * APB + (laneA_g + 2 * j) * 16);
    }

    float m0 = -1e30f, m1 = -1e30f, l0 = 0.0f, l1 = 0.0f;
    float o[8][4];
#pragma unroll
    for (int nt = 0; nt < 8; nt++)
#pragma unroll
        for (int i = 0; i < 4; i++) o[nt][i] = 0.0f;

    for (int kt = 0; kt < NT; kt++) {
        asm volatile("cp.async.wait_group 1;" ::: "memory");
        __syncthreads();
        issue_kv(kt + 2);

        int st = kt - (kt / 3) * 3;
        uint32_t kSt = sK + st * KSTG;
        uint32_t vSt = sV + st * KSTG;

        float s[8][4];
#pragma unroll
        for (int nt = 0; nt < 8; nt++)
#pragma unroll
            for (int i = 0; i < 4; i++) s[nt][i] = 0.0f;

#pragma unroll
        for (int j = 0; j < 4; j++) {
            uint32_t bF[4][4];
#pragma unroll
            for (int np = 0; np < 4; np++) {
                LDSM4(bF[np][0], bF[np][1], bF[np][2], bF[np][3],
                      kSt + (np * 16 + laneB_r) * APB + (laneB_g + 2 * j) * 16);
            }
#pragma unroll
            for (int nt = 0; nt < 8; nt++)
                MMA_BF16(s[nt], qF[j], bF[nt >> 1][(nt & 1) * 2], bF[nt >> 1][(nt & 1) * 2 + 1]);
        }

        float mx0 = -1e30f, mx1 = -1e30f;
#pragma unroll
        for (int nt = 0; nt < 8; nt++) {
            s[nt][0] *= SCALE_LOG2; s[nt][1] *= SCALE_LOG2;
            s[nt][2] *= SCALE_LOG2; s[nt][3] *= SCALE_LOG2;
            mx0 = fmaxf(mx0, fmaxf(s[nt][0], s[nt][1]));
            mx1 = fmaxf(mx1, fmaxf(s[nt][2], s[nt][3]));
        }
        mx0 = fmaxf(mx0, __shfl_xor_sync(0xffffffffu, mx0, 1));
        mx0 = fmaxf(mx0, __shfl_xor_sync(0xffffffffu, mx0, 2));
        mx1 = fmaxf(mx1, __shfl_xor_sync(0xffffffffu, mx1, 1));
        mx1 = fmaxf(mx1, __shfl_xor_sync(0xffffffffu, mx1, 2));
        float nm0 = fmaxf(m0, mx0), nm1 = fmaxf(m1, mx1);
        float a0 = ex2(m0 - nm0), a1 = ex2(m1 - nm1);
        m0 = nm0; m1 = nm1;

#pragma unroll
        for (int nt = 0; nt < 8; nt++) {
            o[nt][0] *= a0; o[nt][1] *= a0;
            o[nt][2] *= a1; o[nt][3] *= a1;
        }
        l0 *= a0;
        l1 *= a1;

#pragma unroll
        for (int j = 0; j < 4; j++) {
#pragma unroll
            for (int u = 0; u < 2; u++) {
                int nt = 2 * j + u;
                s[nt][0] = ex2(s[nt][0] - nm0);
                s[nt][1] = ex2(s[nt][1] - nm0);
                s[nt][2] = ex2(s[nt][2] - nm1);
                s[nt][3] = ex2(s[nt][3] - nm1);
            }
            uint32_t pAj[4];
            pAj[0] = packbf(s[2*j][0],   s[2*j][1]);
            pAj[1] = packbf(s[2*j][2],   s[2*j][3]);
            pAj[2] = packbf(s[2*j+1][0], s[2*j+1][1]);
            pAj[3] = packbf(s[2*j+1][2], s[2*j+1][3]);

            uint32_t tF[4][4];
#pragma unroll
            for (int pr = 0; pr < 4; pr++) {
                uint32_t addr = vSt + (j * 16 + laneV_key) * APB
                                    + (pr * 16 + laneV_doff) * 2;
                LDSM4T(tF[pr][0], tF[pr][1], tF[pr][2], tF[pr][3], addr);
            }
#pragma unroll
            for (int nt = 0; nt < 8; nt++)
                MMA_BF16(o[nt], pAj, tF[nt >> 1][(nt & 1) * 2], tF[nt >> 1][(nt & 1) * 2 + 1]);
        }

        float sum0 = 0.0f, sum1 = 0.0f;
#pragma unroll
        for (int nt = 0; nt < 8; nt++) {
            sum0 += s[nt][0] + s[nt][1];
            sum1 += s[nt][2] + s[nt][3];
        }
        sum0 += __shfl_xor_sync(0xffffffffu, sum0, 1);
        sum0 += __shfl_xor_sync(0xffffffffu, sum0, 2);
        sum1 += __shfl_xor_sync(0xffffffffu, sum1, 1);
        sum1 += __shfl_xor_sync(0xffffffffu, sum1, 2);
        l0 += sum0;
        l1 += sum1;
    }

    float inv0 = 1.0f / l0, inv1 = 1.0f / l1;
    int r0 = qt * 128 + warp * 16 + (lane >> 2);
    int c0 = (lane & 3) * 2;
#pragma unroll
    for (int nt = 0; nt < 8; nt++) {
        size_t p0 = base + (size_t)r0 * D_MODEL + nt * 8 + c0;
        size_t p1 = base + (size_t)(r0 + 8) * D_MODEL + nt * 8 + c0;
        *(__nv_bfloat162*)(Og + p0) = __floats2bfloat162_rn(o[nt][0] * inv0, o[nt][1] * inv0);
        *(__nv_bfloat162*)(Og + p1) = __floats2bfloat162_rn(o[nt][2] * inv1, o[nt][3] * inv1);
    }
}

// ---------------------------------------------------------------------------
// LayerNorm: 4 rows per block (2048 blocks x 256 threads).
// ---------------------------------------------------------------------------
__global__ __launch_bounds__(256)
void ln_kernel(const float* __restrict__ X,
               const float* __restrict__ gamma,
               const float* __restrict__ beta,
               float* __restrict__ out)
{
    const int tid  = threadIdx.x;
    const int warp = tid >> 5, lane = tid & 31;

    float4 gm = *(const float4*)(gamma + tid * 4);
    float4 bt = *(const float4*)(beta  + tid * 4);

    __shared__ float sh[16];

#pragma unroll
    for (int rr = 0; rr < 4; rr++) {
        const int row = blockIdx.x * 4 + rr;
        const float* x = X + (size_t)row * D_MODEL;

        float4 f = *(const float4*)(x + tid * 4);
        float s  = f.x + f.y + f.z + f.w;
        float ss = f.x * f.x + f.y * f.y + f.z * f.z + f.w * f.w;

#pragma unroll
        for (int o = 16; o > 0; o >>= 1) {
            s  += __shfl_xor_sync(0xffffffffu, s,  o);
            ss += __shfl_xor_sync(0xffffffffu, ss, o);
        }
        if (lane == 0) { sh[warp] = s; sh[warp + 8] = ss; }
        __syncthreads();
        if (tid == 0) {
            float S = 0.0f, SS = 0.0f;
#pragma unroll
            for (int w = 0; w < 8; w++) { S += sh[w]; SS += sh[w + 8]; }
            float mu  = S * (1.0f / D_MODEL);
            float var = SS * (1.0f / D_MODEL) - mu * mu;
            sh[0] = mu;
            sh[1] = rsqrtf(var + LN_EPS);
        }
        __syncthreads();
        float mu = sh[0], rstd = sh[1];
        __syncthreads();

        float4 o4;
        o4.x = (f.x - mu) * rstd * gm.x + bt.x;
        o4.y = (f.y - mu) * rstd * gm.y + bt.y;
        o4.z = (f.z - mu) * rstd * gm.z + bt.z;
        o4.w = (f.w - mu) * rstd * gm.w + bt.w;
        *(float4*)(out + (size_t)row * D_MODEL + tid * 4) = o4;
    }
}

// ---------------------------------------------------------------------------
// Launch
// ---------------------------------------------------------------------------
extern "C" void kernel_launch(void* const* d_in, const int* in_sizes, int n_in,
                              void* d_out, int out_size)
{
    const float* batch = (const float*)d_in[0];
    const float* wq    = (const float*)d_in[1];
    const float* bq    = (const float*)d_in[2];
    const float* wk    = (const float*)d_in[3];
    const float* bk    = (const float*)d_in[4];
    const float* wv    = (const float*)d_in[5];
    const float* bv    = (const float*)d_in[6];
    const float* wo    = (const float*)d_in[7];
    const float* bo    = (const float*)d_in[8];
    const float* ln_g  = (const float*)d_in[9];
    const float* ln_b  = (const float*)d_in[10];

    __nv_bfloat16 *qh, *kh, *vh, *ah, *bxh, *wqkvh, *woh;
    float *x;
    cudaGetSymbolAddress((void**)&qh,    g_qh);
    cudaGetSymbolAddress((void**)&kh,    g_kh);
    cudaGetSymbolAddress((void**)&vh,    g_vh);
    cudaGetSymbolAddress((void**)&ah,    g_ah);
    cudaGetSymbolAddress((void**)&bxh,   g_bxh);
    cudaGetSymbolAddress((void**)&wqkvh, g_wqkv);
    cudaGetSymbolAddress((void**)&woh,   g_woh);
    cudaGetSymbolAddress((void**)&x,     g_x);

    static bool attr_done = false;
    if (!attr_done) {
        cudaFuncSetAttribute(gemm_qkv, cudaFuncAttributeMaxDynamicSharedMemorySize, GSM);
        cudaFuncSetAttribute(gemm_out, cudaFuncAttributeMaxDynamicSharedMemorySize, GSM);
        cudaFuncSetAttribute(attn_bf16, cudaFuncAttributeMaxDynamicSharedMemorySize, ASM_TOTAL);
        attr_done = true;
    }

    // Single fused fp32 -> bf16 conversion launch
    const int nb4 = MTOT * D_MODEL / 4;
    const int nw4 = D_MODEL * D_MODEL / 4;
    const int ntot = nb4 + 4 * nw4;
    conv_all_kernel<<<(ntot + 255) / 256, 256>>>(batch, wq, wk, wv, wo,
                                                 bxh, wqkvh, woh);

    // Fused QKV projection: [8192,1024] @ [3072,1024]^T
    dim3 gq(3 * D_MODEL / 128, MTOT / 128);  // (24, 64)
    gemm_qkv<<<gq, 128, GSM>>>(bxh, wqkvh, bq, bk, bv, qh, kh, vh, MTOT, D_MODEL);

    dim3 ga(SEQ / 128, NHEAD, BATCH);        // (16, 16, 4)
    attn_bf16<<<ga, 256, ASM_TOTAL>>>(qh, kh, vh, ah);

    // Out-projection + residual (fp32 out), 256-thread no-spill config
    dim3 gg(D_MODEL / 128, MTOT / 128);      // (8, 64)
    gemm_out<<<gg, 256, GSM>>>(ah, woh, bo, batch, x, MTOT, D_MODEL);

    ln_kernel<<<MTOT / 4, 256>>>(x, ln_g, ln_b, (float*)d_out);
}

// round 17
// speedup vs baseline: 1.0196x; 1.0196x over previous
#include <cuda_runtime.h>
#include <cuda_bf16.h>
#include <cstdint>

#define D_MODEL 1024
#define SEQ     2048
#define BATCH   4
#define NHEAD   16
#define DHEAD   64
#define MTOT    (BATCH*SEQ)   // 8192
#define LN_EPS  1e-5f

// ---------------------------------------------------------------------------
// Scratch (no cudaMalloc allowed). bf16 operands, fp32 where accuracy matters.
// g_bxh doubles as: bf16 batch (pre-QKV), then proj output of gemm_out.
// ---------------------------------------------------------------------------
__device__ __nv_bfloat16 g_qh[(size_t)MTOT * D_MODEL];
__device__ __nv_bfloat16 g_kh[(size_t)MTOT * D_MODEL];
__device__ __nv_bfloat16 g_vh[(size_t)MTOT * D_MODEL];
__device__ __nv_bfloat16 g_ah[(size_t)MTOT * D_MODEL];   // attention output
__device__ __nv_bfloat16 g_bxh[(size_t)MTOT * D_MODEL];  // bf16 batch / proj
__device__ __nv_bfloat16 g_wqkv[(size_t)3 * D_MODEL * D_MODEL]; // packed q,k,v
__device__ __nv_bfloat16 g_woh[(size_t)D_MODEL * D_MODEL];

// ---------------------------------------------------------------------------
// Helpers
// ---------------------------------------------------------------------------
__device__ __forceinline__ uint32_t s2u(const void* p) {
    uint32_t a;
    asm("{ .reg .u64 t; cvta.to.shared.u64 t, %1; cvt.u32.u64 %0, t; }"
        : "=r"(a) : "l"(p));
    return a;
}

#define LDSM4(f0,f1,f2,f3,addr) \
    asm volatile("ldmatrix.sync.aligned.m8n8.x4.shared.b16 {%0,%1,%2,%3}, [%4];" \
                 : "=r"(f0), "=r"(f1), "=r"(f2), "=r"(f3) : "r"(addr))

#define LDSM4T(f0,f1,f2,f3,addr) \
    asm volatile("ldmatrix.sync.aligned.m8n8.x4.trans.shared.b16 {%0,%1,%2,%3}, [%4];" \
                 : "=r"(f0), "=r"(f1), "=r"(f2), "=r"(f3) : "r"(addr))

#define MMA_BF16(d, a, b0, b1) \
    asm volatile("mma.sync.aligned.m16n8k16.row.col.f32.bf16.bf16.f32 " \
                 "{%0,%1,%2,%3}, {%4,%5,%6,%7}, {%8,%9}, {%0,%1,%2,%3};" \
                 : "+f"((d)[0]), "+f"((d)[1]), "+f"((d)[2]), "+f"((d)[3]) \
                 : "r"((a)[0]), "r"((a)[1]), "r"((a)[2]), "r"((a)[3]), \
                   "r"(b0), "r"(b1))

#define CP16(dst, src) \
    asm volatile("cp.async.cg.shared.global [%0], [%1], 16;" \
                 :: "r"(dst), "l"(src) : "memory")

__device__ __forceinline__ uint32_t packbf(float a, float b) {
    __nv_bfloat162 h = __floats2bfloat162_rn(a, b);
    return *(uint32_t*)&h;
}

// Raw MUFU exp2 (single EX2, no pre-multiply)
__device__ __forceinline__ float ex2(float x) {
    float r;
    asm("ex2.approx.f32 %0, %1;" : "=f"(r) : "f"(x));
    return r;
}

// ---------------------------------------------------------------------------
// Single fused fp32 -> bf16 conversion kernel
// ---------------------------------------------------------------------------
__global__ __launch_bounds__(256)
void conv_all_kernel(const float* __restrict__ batch,
                     const float* __restrict__ wq, const float* __restrict__ wk,
                     const float* __restrict__ wv, const float* __restrict__ wo,
                     __nv_bfloat16* __restrict__ bxh,
                     __nv_bfloat16* __restrict__ wqkv,
                     __nv_bfloat16* __restrict__ woh)
{
    const int nb4 = MTOT * D_MODEL / 4;
    const int nw4 = D_MODEL * D_MODEL / 4;
    int i = blockIdx.x * blockDim.x + threadIdx.x;

    const float* src;
    __nv_bfloat16* dst;
    int j;
    if (i < nb4) {
        src = batch; dst = bxh; j = i;
    } else {
        int k = i - nb4;
        if (k < 3 * nw4) {
            int w = k / nw4;
            j = k - w * nw4;
            src = (w == 0) ? wq : (w == 1) ? wk : wv;
            dst = wqkv + (size_t)w * D_MODEL * D_MODEL;
        } else {
            j = k - 3 * nw4;
            if (j >= nw4) return;
            src = wo; dst = woh;
        }
    }
    float4 f = ((const float4*)src)[j];
    ((__nv_bfloat162*)dst)[j * 2]     = __floats2bfloat162_rn(f.x, f.y);
    ((__nv_bfloat162*)dst)[j * 2 + 1] = __floats2bfloat162_rn(f.z, f.w);
}

// ---------------------------------------------------------------------------
// QKV GEMM (unchanged — measured plateau): CTA 128x128, 128 threads = 4 warps,
// warp tile 64x64, BK=64, NS=3 cp.async ring, bf16 outputs routed by segment.
// ---------------------------------------------------------------------------
#define GPH   72                    // halves per smem row (64 data + 8 pad)
#define GSTGB (128 * GPH * 2)       // 18432 bytes per operand per stage
#define GSM   (3 * 2 * GSTGB)       // 110592 bytes dynamic smem

__global__ __launch_bounds__(128, 2)
void gemm_qkv(const __nv_bfloat16* __restrict__ A, const __nv_bfloat16* __restrict__ W,
              const float* __restrict__ b0p, const float* __restrict__ b1p,
              const float* __restrict__ b2p,
              __nv_bfloat16* __restrict__ o0p, __nv_bfloat16* __restrict__ o1p,
              __nv_bfloat16* __restrict__ o2p,
              int M, int K)
{
    extern __shared__ __align__(16) char gsm[];
    const uint32_t sA = s2u(gsm);
    const uint32_t sB = sA + 3 * GSTGB;

    const int tid  = threadIdx.x;
    const int wid  = tid >> 5;
    const int lane = tid & 31;
    const int wm   = wid & 1;
    const int wn   = wid >> 1;
    const int m0   = blockIdx.y * 128;
    const int n0   = blockIdx.x * 128;
    const int NCH  = K / 64;               // 16

    int seg = n0 >> 10;
    const float* bias = (seg == 0) ? b0p : (seg == 1) ? b1p : b2p;
    __nv_bfloat16* Cb = (seg == 0) ? o0p : (seg == 1) ? o1p : o2p;
    int nloc0 = n0 & 1023;

    const int r_ld = tid >> 3;
    const int g_ld = tid & 7;
    const __nv_bfloat16* Abase = A + (size_t)m0 * K + g_ld * 8;
    const __nv_bfloat16* Wbase = W + (size_t)n0 * K + g_ld * 8;

    auto issue = [&](int c) {
        if (c < NCH) {
            int st = c - (c / 3) * 3;
            uint32_t da = sA + st * GSTGB;
            uint32_t db = sB + st * GSTGB;
            long ko = (long)c * 64;
#pragma unroll
            for (int q = 0; q < 8; q++) {
                int row = r_ld + q * 16;
                CP16(da + row * (GPH * 2) + g_ld * 16, Abase + (size_t)row * K + ko);
                CP16(db + row * (GPH * 2) + g_ld * 16, Wbase + (size_t)row * K + ko);
            }
        }
        asm volatile("cp.async.commit_group;" ::: "memory");
    };

    float acc[4][8][4];
#pragma unroll
    for (int i = 0; i < 4; i++)
#pragma unroll
        for (int j = 0; j < 8; j++)
#pragma unroll
            for (int k = 0; k < 4; k++) acc[i][j][k] = 0.0f;

    const int laneA_r = ((lane >> 3) & 1) * 8 + (lane & 7);
    const int laneA_g = lane >> 4;
    const int laneB_r = (lane >> 4) * 8 + (lane & 7);
    const int laneB_g = (lane >> 3) & 1;

    issue(0); issue(1);

    for (int c = 0; c < NCH; c++) {
        asm volatile("cp.async.wait_group 1;" ::: "memory");
        __syncthreads();
        issue(c + 2);

        int st = c - (c / 3) * 3;
        uint32_t aSt = sA + st * GSTGB;
        uint32_t bSt = sB + st * GSTGB;

#pragma unroll
        for (int j = 0; j < 4; j++) {
            uint32_t aF[4][4], bF[4][4];
#pragma unroll
            for (int mt = 0; mt < 4; mt++) {
                uint32_t addr = aSt + (wm * 64 + mt * 16 + laneA_r) * (GPH * 2)
                                    + (laneA_g + 2 * j) * 16;
                LDSM4(aF[mt][0], aF[mt][1], aF[mt][2], aF[mt][3], addr);
            }
#pragma unroll
            for (int np = 0; np < 4; np++) {
                uint32_t addr = bSt + (wn * 64 + np * 16 + laneB_r) * (GPH * 2)
                                    + (laneB_g + 2 * j) * 16;
                LDSM4(bF[np][0], bF[np][1], bF[np][2], bF[np][3], addr);
            }
#pragma unroll
            for (int mt = 0; mt < 4; mt++) {
#pragma unroll
                for (int nt = 0; nt < 8; nt++) {
                    MMA_BF16(acc[mt][nt], aF[mt],
                             bF[nt >> 1][(nt & 1) * 2], bF[nt >> 1][(nt & 1) * 2 + 1]);
                }
            }
        }
    }

    const int rb = lane >> 2;
    const int cb = (lane & 3) * 2;
#pragma unroll
    for (int mt = 0; mt < 4; mt++) {
#pragma unroll
        for (int nt = 0; nt < 8; nt++) {
            int nl = nloc0 + wn * 64 + nt * 8 + cb;
            float2 bv = *(const float2*)(bias + nl);
            int row0 = m0 + wm * 64 + mt * 16 + rb;
            int row1 = row0 + 8;
            *(__nv_bfloat162*)(Cb + (size_t)row0 * D_MODEL + nl) =
                __floats2bfloat162_rn(acc[mt][nt][0] + bv.x, acc[mt][nt][1] + bv.y);
            *(__nv_bfloat162*)(Cb + (size_t)row1 * D_MODEL + nl) =
                __floats2bfloat162_rn(acc[mt][nt][2] + bv.x, acc[mt][nt][3] + bv.y);
        }
    }
}

// ---------------------------------------------------------------------------
// Out-projection GEMM (+bias -> bf16 proj; residual deferred to LN):
// 256 threads = 8 warps, warp grid 2(m) x 4(n), warp tile 64x32.
// Same BK=64, NS=3 cp.async ring. Epilogue is a lean 16MB bf16 write.
// ---------------------------------------------------------------------------
__global__ __launch_bounds__(256, 2)
void gemm_out(const __nv_bfloat16* __restrict__ A, const __nv_bfloat16* __restrict__ W,
              const float* __restrict__ bias,
              __nv_bfloat16* __restrict__ Ob,
              int M, int K)
{
    extern __shared__ __align__(16) char gsm[];
    const uint32_t sA = s2u(gsm);
    const uint32_t sB = sA + 3 * GSTGB;

    const int tid  = threadIdx.x;
    const int wid  = tid >> 5;
    const int lane = tid & 31;
    const int wm   = wid & 1;        // 0..1
    const int wn   = wid >> 1;       // 0..3
    const int m0   = blockIdx.y * 128;
    const int n0   = blockIdx.x * 128;
    const int NCH  = K / 64;               // 16

    const int g_ld = tid & 7;        // granule
    const int r4   = tid >> 3;       // 0..31 base row
    const __nv_bfloat16* Abase = A + (size_t)m0 * K + g_ld * 8;
    const __nv_bfloat16* Wbase = W + (size_t)n0 * K + g_ld * 8;

    auto issue = [&](int c) {
        if (c < NCH) {
            int st = c - (c / 3) * 3;
            uint32_t da = sA + st * GSTGB;
            uint32_t db = sB + st * GSTGB;
            long ko = (long)c * 64;
#pragma unroll
            for (int q = 0; q < 4; q++) {
                int row = r4 + q * 32;
                CP16(da + row * (GPH * 2) + g_ld * 16, Abase + (size_t)row * K + ko);
                CP16(db + row * (GPH * 2) + g_ld * 16, Wbase + (size_t)row * K + ko);
            }
        }
        asm volatile("cp.async.commit_group;" ::: "memory");
    };

    float acc[4][4][4];
#pragma unroll
    for (int i = 0; i < 4; i++)
#pragma unroll
        for (int j = 0; j < 4; j++)
#pragma unroll
            for (int k = 0; k < 4; k++) acc[i][j][k] = 0.0f;

    const int laneA_r = ((lane >> 3) & 1) * 8 + (lane & 7);
    const int laneA_g = lane >> 4;
    const int laneB_r = (lane >> 4) * 8 + (lane & 7);
    const int laneB_g = (lane >> 3) & 1;

    issue(0); issue(1);

    for (int c = 0; c < NCH; c++) {
        asm volatile("cp.async.wait_group 1;" ::: "memory");
        __syncthreads();
        issue(c + 2);

        int st = c - (c / 3) * 3;
        uint32_t aSt = sA + st * GSTGB;
        uint32_t bSt = sB + st * GSTGB;

#pragma unroll
        for (int j = 0; j < 4; j++) {
            uint32_t aF[4][4], bF[2][4];
#pragma unroll
            for (int mt = 0; mt < 4; mt++) {
                uint32_t addr = aSt + (wm * 64 + mt * 16 + laneA_r) * (GPH * 2)
                                    + (laneA_g + 2 * j) * 16;
                LDSM4(aF[mt][0], aF[mt][1], aF[mt][2], aF[mt][3], addr);
            }
#pragma unroll
            for (int np = 0; np < 2; np++) {
                uint32_t addr = bSt + (wn * 32 + np * 16 + laneB_r) * (GPH * 2)
                                    + (laneB_g + 2 * j) * 16;
                LDSM4(bF[np][0], bF[np][1], bF[np][2], bF[np][3], addr);
            }
#pragma unroll
            for (int mt = 0; mt < 4; mt++) {
#pragma unroll
                for (int nt = 0; nt < 4; nt++) {
                    MMA_BF16(acc[mt][nt], aF[mt],
                             bF[nt >> 1][(nt & 1) * 2], bF[nt >> 1][(nt & 1) * 2 + 1]);
                }
            }
        }
    }

    const int rb = lane >> 2;
    const int cb = (lane & 3) * 2;
#pragma unroll
    for (int mt = 0; mt < 4; mt++) {
#pragma unroll
        for (int nt = 0; nt < 4; nt++) {
            int nl = n0 + wn * 32 + nt * 8 + cb;
            float2 bv = *(const float2*)(bias + nl);
            int row0 = m0 + wm * 64 + mt * 16 + rb;
            int row1 = row0 + 8;
            *(__nv_bfloat162*)(Ob + (size_t)row0 * D_MODEL + nl) =
                __floats2bfloat162_rn(acc[mt][nt][0] + bv.x, acc[mt][nt][1] + bv.y);
            *(__nv_bfloat162*)(Ob + (size_t)row1 * D_MODEL + nl) =
                __floats2bfloat162_rn(acc[mt][nt][2] + bv.x, acc[mt][nt][3] + bv.y);
        }
    }
}

// ---------------------------------------------------------------------------
// bf16 tensor-core flash attention (fp32 accum + softmax), exp2 domain.
// UNCHANGED (at the mma.sync plateau).
// ---------------------------------------------------------------------------
#define APH    72
#define APB    (APH * 2)            // 144 bytes row pitch
#define KSTG   (64 * APB)           // 9216 per stage
#define AOFF_K  0
#define AOFF_V  (3 * KSTG)           // 27648
#define AOFF_Q  (6 * KSTG)           // 55296
#define ASM_TOTAL (AOFF_Q + 128 * APB) // 73728

#define SCALE_LOG2 0.1803368801111244f   // 0.125 * log2(e)

__global__ __launch_bounds__(256, 2)
void attn_bf16(const __nv_bfloat16* __restrict__ Q,
               const __nv_bfloat16* __restrict__ Kg,
               const __nv_bfloat16* __restrict__ Vg,
               __nv_bfloat16* __restrict__ Og)
{
    extern __shared__ __align__(16) char asmem[];
    const uint32_t sb = s2u(asmem);
    const uint32_t sK = sb + AOFF_K;
    const uint32_t sV = sb + AOFF_V;
    const uint32_t sQ = sb + AOFF_Q;
    __nv_bfloat16* smQ = (__nv_bfloat16*)(asmem + AOFF_Q);

    const int qt   = blockIdx.x;
    const int h    = blockIdx.y;
    const int b    = blockIdx.z;
    const int tid  = threadIdx.x;
    const int warp = tid >> 5;
    const int lane = tid & 31;

    const size_t base = ((size_t)b * SEQ) * D_MODEL + (size_t)h * DHEAD;
    const int NT = SEQ / 64;  // 32

    auto issue_kv = [&](int kt) {
        if (kt < NT) {
            int st = kt - (kt / 3) * 3;
            uint32_t kd = sK + st * KSTG;
            uint32_t vd = sV + st * KSTG;
            const __nv_bfloat16* kp = Kg + base + (size_t)(kt * 64) * D_MODEL;
            const __nv_bfloat16* vp = Vg + base + (size_t)(kt * 64) * D_MODEL;
#pragma unroll
            for (int q = 0; q < 2; q++) {
                int id = tid + q * 256;
                int r = id >> 3, g = id & 7;
                CP16(kd + r * APB + g * 16, kp + (size_t)r * D_MODEL + g * 8);
                CP16(vd + r * APB + g * 16, vp + (size_t)r * D_MODEL + g * 8);
            }
        }
        asm volatile("cp.async.commit_group;" ::: "memory");
    };

    issue_kv(0);
    issue_kv(1);

    for (int i = tid; i < 1024; i += 256) {
        int r = i >> 3;
        int g = i & 7;
        uint4 f = *(const uint4*)(Q + base + (size_t)(qt * 128 + r) * D_MODEL + g * 8);
        *(uint4*)(smQ + r * APH + g * 8) = f;
    }
    __syncthreads();

    const int laneA_r = ((lane >> 3) & 1) * 8 + (lane & 7);
    const int laneA_g = lane >> 4;
    const int laneB_r = (lane >> 4) * 8 + (lane & 7);
    const int laneB_g = (lane >> 3) & 1;
    const int laneV_key  = ((lane >> 3) & 1) * 8 + (lane & 7);
    const int laneV_doff = (lane >> 4) * 8;

    uint32_t qF[4][4];
#pragma unroll
    for (int j = 0; j < 4; j++) {
        LDSM4(qF[j][0], qF[j][1], qF[j][2], qF[j][3],
              sQ + (warp * 16 + laneA_r) * APB + (laneA_g + 2 * j) * 16);
    }

    float m0 = -1e30f, m1 = -1e30f, l0 = 0.0f, l1 = 0.0f;
    float o[8][4];
#pragma unroll
    for (int nt = 0; nt < 8; nt++)
#pragma unroll
        for (int i = 0; i < 4; i++) o[nt][i] = 0.0f;

    for (int kt = 0; kt < NT; kt++) {
        asm volatile("cp.async.wait_group 1;" ::: "memory");
        __syncthreads();
        issue_kv(kt + 2);

        int st = kt - (kt / 3) * 3;
        uint32_t kSt = sK + st * KSTG;
        uint32_t vSt = sV + st * KSTG;

        float s[8][4];
#pragma unroll
        for (int nt = 0; nt < 8; nt++)
#pragma unroll
            for (int i = 0; i < 4; i++) s[nt][i] = 0.0f;

#pragma unroll
        for (int j = 0; j < 4; j++) {
            uint32_t bF[4][4];
#pragma unroll
            for (int np = 0; np < 4; np++) {
                LDSM4(bF[np][0], bF[np][1], bF[np][2], bF[np][3],
                      kSt + (np * 16 + laneB_r) * APB + (laneB_g + 2 * j) * 16);
            }
#pragma unroll
            for (int nt = 0; nt < 8; nt++)
                MMA_BF16(s[nt], qF[j], bF[nt >> 1][(nt & 1) * 2], bF[nt >> 1][(nt & 1) * 2 + 1]);
        }

        float mx0 = -1e30f, mx1 = -1e30f;
#pragma unroll
        for (int nt = 0; nt < 8; nt++) {
            s[nt][0] *= SCALE_LOG2; s[nt][1] *= SCALE_LOG2;
            s[nt][2] *= SCALE_LOG2; s[nt][3] *= SCALE_LOG2;
            mx0 = fmaxf(mx0, fmaxf(s[nt][0], s[nt][1]));
            mx1 = fmaxf(mx1, fmaxf(s[nt][2], s[nt][3]));
        }
        mx0 = fmaxf(mx0, __shfl_xor_sync(0xffffffffu, mx0, 1));
        mx0 = fmaxf(mx0, __shfl_xor_sync(0xffffffffu, mx0, 2));
        mx1 = fmaxf(mx1, __shfl_xor_sync(0xffffffffu, mx1, 1));
        mx1 = fmaxf(mx1, __shfl_xor_sync(0xffffffffu, mx1, 2));
        float nm0 = fmaxf(m0, mx0), nm1 = fmaxf(m1, mx1);
        float a0 = ex2(m0 - nm0), a1 = ex2(m1 - nm1);
        m0 = nm0; m1 = nm1;

#pragma unroll
        for (int nt = 0; nt < 8; nt++) {
            o[nt][0] *= a0; o[nt][1] *= a0;
            o[nt][2] *= a1; o[nt][3] *= a1;
        }
        l0 *= a0;
        l1 *= a1;

#pragma unroll
        for (int j = 0; j < 4; j++) {
#pragma unroll
            for (int u = 0; u < 2; u++) {
                int nt = 2 * j + u;
                s[nt][0] = ex2(s[nt][0] - nm0);
                s[nt][1] = ex2(s[nt][1] - nm0);
                s[nt][2] = ex2(s[nt][2] - nm1);
                s[nt][3] = ex2(s[nt][3] - nm1);
            }
            uint32_t pAj[4];
            pAj[0] = packbf(s[2*j][0],   s[2*j][1]);
            pAj[1] = packbf(s[2*j][2],   s[2*j][3]);
            pAj[2] = packbf(s[2*j+1][0], s[2*j+1][1]);
            pAj[3] = packbf(s[2*j+1][2], s[2*j+1][3]);

            uint32_t tF[4][4];
#pragma unroll
            for (int pr = 0; pr < 4; pr++) {
                uint32_t addr = vSt + (j * 16 + laneV_key) * APB
                                    + (pr * 16 + laneV_doff) * 2;
                LDSM4T(tF[pr][0], tF[pr][1], tF[pr][2], tF[pr][3], addr);
            }
#pragma unroll
            for (int nt = 0; nt < 8; nt++)
                MMA_BF16(o[nt], pAj, tF[nt >> 1][(nt & 1) * 2], tF[nt >> 1][(nt & 1) * 2 + 1]);
        }

        float sum0 = 0.0f, sum1 = 0.0f;
#pragma unroll
        for (int nt = 0; nt < 8; nt++) {
            sum0 += s[nt][0] + s[nt][1];
            sum1 += s[nt][2] + s[nt][3];
        }
        sum0 += __shfl_xor_sync(0xffffffffu, sum0, 1);
        sum0 += __shfl_xor_sync(0xffffffffu, sum0, 2);
        sum1 += __shfl_xor_sync(0xffffffffu, sum1, 1);
        sum1 += __shfl_xor_sync(0xffffffffu, sum1, 2);
        l0 += sum0;
        l1 += sum1;
    }

    float inv0 = 1.0f / l0, inv1 = 1.0f / l1;
    int r0 = qt * 128 + warp * 16 + (lane >> 2);
    int c0 = (lane & 3) * 2;
#pragma unroll
    for (int nt = 0; nt < 8; nt++) {
        size_t p0 = base + (size_t)r0 * D_MODEL + nt * 8 + c0;
        size_t p1 = base + (size_t)(r0 + 8) * D_MODEL + nt * 8 + c0;
        *(__nv_bfloat162*)(Og + p0) = __floats2bfloat162_rn(o[nt][0] * inv0, o[nt][1] * inv0);
        *(__nv_bfloat162*)(Og + p1) = __floats2bfloat162_rn(o[nt][2] * inv1, o[nt][3] * inv1);
    }
}

// ---------------------------------------------------------------------------
// Fused residual + LayerNorm: x = batch(fp32) + proj(bf16), then normalize.
// 4 rows per block (2048 blocks x 256 threads).
// ---------------------------------------------------------------------------
__global__ __launch_bounds__(256)
void ln_kernel(const float* __restrict__ batch,
               const __nv_bfloat16* __restrict__ proj,
               const float* __restrict__ gamma,
               const float* __restrict__ beta,
               float* __restrict__ out)
{
    const int tid  = threadIdx.x;
    const int warp = tid >> 5, lane = tid & 31;

    float4 gm = *(const float4*)(gamma + tid * 4);
    float4 bt = *(const float4*)(beta  + tid * 4);

    __shared__ float sh[16];

#pragma unroll
    for (int rr = 0; rr < 4; rr++) {
        const int row = blockIdx.x * 4 + rr;
        const float* xb = batch + (size_t)row * D_MODEL;
        const __nv_bfloat16* xp = proj + (size_t)row * D_MODEL;

        float4 f = *(const float4*)(xb + tid * 4);
        __nv_bfloat162 p01 = *(const __nv_bfloat162*)(xp + tid * 4);
        __nv_bfloat162 p23 = *(const __nv_bfloat162*)(xp + tid * 4 + 2);
        f.x += __bfloat162float(p01.x);
        f.y += __bfloat162float(p01.y);
        f.z += __bfloat162float(p23.x);
        f.w += __bfloat162float(p23.y);

        float s  = f.x + f.y + f.z + f.w;
        float ss = f.x * f.x + f.y * f.y + f.z * f.z + f.w * f.w;

#pragma unroll
        for (int o = 16; o > 0; o >>= 1) {
            s  += __shfl_xor_sync(0xffffffffu, s,  o);
            ss += __shfl_xor_sync(0xffffffffu, ss, o);
        }
        if (lane == 0) { sh[warp] = s; sh[warp + 8] = ss; }
        __syncthreads();
        if (tid == 0) {
            float S = 0.0f, SS = 0.0f;
#pragma unroll
            for (int w = 0; w < 8; w++) { S += sh[w]; SS += sh[w + 8]; }
            float mu  = S * (1.0f / D_MODEL);
            float var = SS * (1.0f / D_MODEL) - mu * mu;
            sh[0] = mu;
            sh[1] = rsqrtf(var + LN_EPS);
        }
        __syncthreads();
        float mu = sh[0], rstd = sh[1];
        __syncthreads();

        float4 o4;
        o4.x = (f.x - mu) * rstd * gm.x + bt.x;
        o4.y = (f.y - mu) * rstd * gm.y + bt.y;
        o4.z = (f.z - mu) * rstd * gm.z + bt.z;
        o4.w = (f.w - mu) * rstd * gm.w + bt.w;
        *(float4*)(out + (size_t)row * D_MODEL + tid * 4) = o4;
    }
}

// ---------------------------------------------------------------------------
// Launch
// ---------------------------------------------------------------------------
extern "C" void kernel_launch(void* const* d_in, const int* in_sizes, int n_in,
                              void* d_out, int out_size)
{
    const float* batch = (const float*)d_in[0];
    const float* wq    = (const float*)d_in[1];
    const float* bq    = (const float*)d_in[2];
    const float* wk    = (const float*)d_in[3];
    const float* bk    = (const float*)d_in[4];
    const float* wv    = (const float*)d_in[5];
    const float* bv    = (const float*)d_in[6];
    const float* wo    = (const float*)d_in[7];
    const float* bo    = (const float*)d_in[8];
    const float* ln_g  = (const float*)d_in[9];
    const float* ln_b  = (const float*)d_in[10];

    __nv_bfloat16 *qh, *kh, *vh, *ah, *bxh, *wqkvh, *woh;
    cudaGetSymbolAddress((void**)&qh,    g_qh);
    cudaGetSymbolAddress((void**)&kh,    g_kh);
    cudaGetSymbolAddress((void**)&vh,    g_vh);
    cudaGetSymbolAddress((void**)&ah,    g_ah);
    cudaGetSymbolAddress((void**)&bxh,   g_bxh);
    cudaGetSymbolAddress((void**)&wqkvh, g_wqkv);
    cudaGetSymbolAddress((void**)&woh,   g_woh);

    // Idempotent, outside graph capture; call unconditionally (no static state).
    cudaFuncSetAttribute(gemm_qkv, cudaFuncAttributeMaxDynamicSharedMemorySize, GSM);
    cudaFuncSetAttribute(gemm_out, cudaFuncAttributeMaxDynamicSharedMemorySize, GSM);
    cudaFuncSetAttribute(attn_bf16, cudaFuncAttributeMaxDynamicSharedMemorySize, ASM_TOTAL);

    // Single fused fp32 -> bf16 conversion launch
    const int nb4 = MTOT * D_MODEL / 4;
    const int nw4 = D_MODEL * D_MODEL / 4;
    const int ntot = nb4 + 4 * nw4;
    conv_all_kernel<<<(ntot + 255) / 256, 256>>>(batch, wq, wk, wv, wo,
                                                 bxh, wqkvh, woh);

    // Fused QKV projection: [8192,1024] @ [3072,1024]^T
    dim3 gq(3 * D_MODEL / 128, MTOT / 128);  // (24, 64)
    gemm_qkv<<<gq, 128, GSM>>>(bxh, wqkvh, bq, bk, bv, qh, kh, vh, MTOT, D_MODEL);

    dim3 ga(SEQ / 128, NHEAD, BATCH);        // (16, 16, 4)
    attn_bf16<<<ga, 256, ASM_TOTAL>>>(qh, kh, vh, ah);

    // Out-projection + bias -> bf16 proj (reuses bxh; residual deferred to LN)
    dim3 gg(D_MODEL / 128, MTOT / 128);      // (8, 64)
    gemm_out<<<gg, 256, GSM>>>(ah, woh, bo, bxh, MTOT, D_MODEL);

    // Fused residual + LayerNorm
    ln_kernel<<<MTOT / 4, 256>>>(batch, bxh, ln_g, ln_b, (float*)d_out);
}